// round 1
// baseline (speedup 1.0000x reference)
#include <cuda_runtime.h>
#include <math.h>

#define BATCH 4
#define CH    64
#define HH    192
#define WWID  192
#define HW    (HH*WWID)
#define BHW   (BATCH*HW)

// ---------------- device scratch (allocation-free) ----------------
__device__ float g_x1 [BHW*CH];      // NHWC
__device__ float g_x2 [BHW*CH];      // NHWC
__device__ float g_y  [BHW*CH];      // NHWC ping-pong
__device__ float g_off[BHW*98];      // NHWC offsets (max 98 ch)
__device__ float g_wA [25*64*112];   // transposed offset-conv weights [tap][c][ocPad]
__device__ float g_wB [49*64*64];    // transposed deform weights     [tap][c][oc]

// ---------------- weight transpose: w[O][C][K][K] -> out[tap][c][ocPad] ----
__global__ void k_transpose(const float* __restrict__ w, float* __restrict__ out,
                            int K2, int KOUT, int KOUTP) {
    int n = K2 * 64 * KOUTP;
    for (int idx = blockIdx.x * blockDim.x + threadIdx.x; idx < n;
         idx += gridDim.x * blockDim.x) {
        int oc  = idx % KOUTP;
        int c   = (idx / KOUTP) % 64;
        int tap = idx / (KOUTP * 64);
        out[idx] = (oc < KOUT) ? w[(oc * 64 + c) * K2 + tap] : 0.f;
    }
}

// ---------------- fused LayerNorm + 1x1 conv (w_in: 64 -> 128) -------------
// NCHW input -> NHWC x1 (o<64) and x2 (o>=64). One warp per pixel.
__global__ __launch_bounds__(256) void k_ln_win(
    const float* __restrict__ x, const float* __restrict__ ln_w,
    const float* __restrict__ ln_b, const float* __restrict__ w_in,
    const float* __restrict__ b_in, float* __restrict__ out1,
    float* __restrict__ out2)
{
    __shared__ float wT[64 * 128];   // [c][o]
    __shared__ float hb[8][64];
    int tid = threadIdx.x;
    for (int idx = tid; idx < 8192; idx += 256) {
        int o = idx >> 6, c = idx & 63;
        wT[c * 128 + o] = w_in[idx];
    }
    int wp = tid >> 5, lane = tid & 31;
    int pg = blockIdx.x * 8 + wp;
    int b = pg / HW, hw = pg % HW;
    const float* xb = x + (size_t)b * CH * HW + hw;
    float v0 = xb[(size_t)lane * HW];
    float v1 = xb[(size_t)(lane + 32) * HW];
    float s = v0 + v1, q = v0 * v0 + v1 * v1;
    #pragma unroll
    for (int o = 16; o; o >>= 1) {
        s += __shfl_xor_sync(0xffffffffu, s, o);
        q += __shfl_xor_sync(0xffffffffu, q, o);
    }
    float mu  = s * (1.f / 64.f);
    float var = q * (1.f / 64.f) - mu * mu;
    float rs  = rsqrtf(var + 1e-5f);
    hb[wp][lane]      = (v0 - mu) * rs * ln_w[lane]      + ln_b[lane];
    hb[wp][lane + 32] = (v1 - mu) * rs * ln_w[lane + 32] + ln_b[lane + 32];
    __syncthreads();
    float a0 = b_in[lane], a1 = b_in[lane + 32];
    float a2 = b_in[lane + 64], a3 = b_in[lane + 96];
    #pragma unroll 8
    for (int c = 0; c < 64; c++) {
        float hv = hb[wp][c];
        const float* wr = &wT[c * 128 + lane];
        a0 += hv * wr[0];  a1 += hv * wr[32];
        a2 += hv * wr[64]; a3 += hv * wr[96];
    }
    float* o1 = out1 + (size_t)pg * 64;
    float* o2 = out2 + (size_t)pg * 64;
    o1[lane] = a0; o1[lane + 32] = a1;
    o2[lane] = a2; o2[lane + 32] = a3;
}

// ---------------- dense KxK conv (offset predictor), NHWC -------------------
// 8x8 pixel tile per block. 256 thr = 16 pxGroups x 16 ocGroups.
template<int K, int PAD, int KOUT, int KOUTP>
__global__ __launch_bounds__(256) void k_conv(
    const float* __restrict__ in, const float* __restrict__ wT,
    const float* __restrict__ bias, float* __restrict__ out)
{
    constexpr int OCT = KOUTP / 16;
    __shared__ float st[64 * 65];        // shifted tile [px][c], padded
    __shared__ float ws[64 * KOUTP];     // [c][oc]
    int tid = threadIdx.x;
    int b   = blockIdx.z;
    int y0  = blockIdx.y * 8, x0 = blockIdx.x * 8;
    int pxg = tid >> 4, ocg = tid & 15;
    float acc[4][OCT];
    #pragma unroll
    for (int i = 0; i < 4; i++)
        #pragma unroll
        for (int j = 0; j < OCT; j++) acc[i][j] = 0.f;

    for (int tap = 0; tap < K * K; tap++) {
        int ki = tap / K, kj = tap % K;
        __syncthreads();
        #pragma unroll
        for (int i = 0; i < 16; i++) {
            int v = i * 256 + tid;
            int p = v >> 6, c = v & 63;
            int yy = y0 + (p >> 3) + ki - PAD;
            int xx = x0 + (p & 7)  + kj - PAD;
            float val = 0.f;
            if (yy >= 0 && yy < HH && xx >= 0 && xx < WWID)
                val = in[((size_t)((b * HH + yy) * WWID + xx)) * 64 + c];
            st[p * 65 + c] = val;
        }
        const float* wsl = wT + (size_t)tap * 64 * KOUTP;
        for (int idx = tid; idx < 64 * KOUTP; idx += 256) ws[idx] = wsl[idx];
        __syncthreads();
        #pragma unroll 4
        for (int c = 0; c < 64; c++) {
            float iv[4];
            #pragma unroll
            for (int i = 0; i < 4; i++) iv[i] = st[(pxg * 4 + i) * 65 + c];
            #pragma unroll
            for (int j = 0; j < OCT; j++) {
                float wv = ws[c * KOUTP + ocg * OCT + j];
                #pragma unroll
                for (int i = 0; i < 4; i++) acc[i][j] += iv[i] * wv;
            }
        }
    }
    #pragma unroll
    for (int i = 0; i < 4; i++) {
        int p = pxg * 4 + i;
        int yy = y0 + (p >> 3), xx = x0 + (p & 7);
        size_t pg = (size_t)(b * HH + yy) * WWID + xx;
        #pragma unroll
        for (int j = 0; j < OCT; j++) {
            int oc = ocg * OCT + j;
            if (oc < KOUT) out[pg * KOUT + oc] = acc[i][j] + bias[oc];
        }
    }
}

// ---------------- deformable KxK conv (Cout = 64), NHWC ---------------------
template<int K, int PAD, int KOFF>
__global__ __launch_bounds__(256) void k_deform(
    const float* __restrict__ in, const float* __restrict__ off,
    const float* __restrict__ wT, const float* __restrict__ bias,
    float* __restrict__ out)
{
    __shared__ float st[64 * 65];    // bilinear-sampled tile [px][c]
    __shared__ float ws[64 * 64];    // [c][oc]
    __shared__ int   s_y0[64], s_x0[64];
    __shared__ float s_wy[64], s_wx[64];
    int tid = threadIdx.x;
    int b   = blockIdx.z;
    int ty0 = blockIdx.y * 8, tx0 = blockIdx.x * 8;
    int pxg = tid >> 4, ocg = tid & 15;
    float acc[4][4] = {};

    for (int tap = 0; tap < K * K; tap++) {
        int ki = tap / K, kj = tap % K;
        __syncthreads();
        if (tid < 64) {
            int yy = ty0 + (tid >> 3), xx = tx0 + (tid & 7);
            size_t pg = (size_t)(b * HH + yy) * WWID + xx;
            float oy = off[pg * KOFF + 2 * tap];
            float ox = off[pg * KOFF + 2 * tap + 1];
            float py = (float)yy + (float)(ki - PAD) + oy;
            float px = (float)xx + (float)(kj - PAD) + ox;
            float fy = floorf(py), fx = floorf(px);
            s_y0[tid] = (int)fy; s_x0[tid] = (int)fx;
            s_wy[tid] = py - fy; s_wx[tid] = px - fx;
        }
        const float* wsl = wT + (size_t)tap * 64 * 64;
        for (int idx = tid; idx < 4096; idx += 256) ws[idx] = wsl[idx];
        __syncthreads();
        #pragma unroll
        for (int i = 0; i < 16; i++) {
            int v = i * 256 + tid;
            int p = v >> 6, c = v & 63;
            int y0i = s_y0[p], x0i = s_x0[p];
            float wy = s_wy[p], wx = s_wx[p];
            bool yv0 = (y0i >= 0)     && (y0i < HH);
            bool yv1 = (y0i + 1 >= 0) && (y0i + 1 < HH);
            bool xv0 = (x0i >= 0)     && (x0i < WWID);
            bool xv1 = (x0i + 1 >= 0) && (x0i + 1 < WWID);
            size_t base = (size_t)b * HW;
            float v00 = 0.f, v01 = 0.f, v10 = 0.f, v11 = 0.f;
            if (yv0 && xv0) v00 = in[(base + (size_t)y0i * WWID + x0i) * 64 + c];
            if (yv0 && xv1) v01 = in[(base + (size_t)y0i * WWID + x0i + 1) * 64 + c];
            if (yv1 && xv0) v10 = in[(base + (size_t)(y0i + 1) * WWID + x0i) * 64 + c];
            if (yv1 && xv1) v11 = in[(base + (size_t)(y0i + 1) * WWID + x0i + 1) * 64 + c];
            st[p * 65 + c] = v00 * (1.f - wy) * (1.f - wx) + v01 * (1.f - wy) * wx
                           + v10 * wy * (1.f - wx)         + v11 * wy * wx;
        }
        __syncthreads();
        #pragma unroll 4
        for (int c = 0; c < 64; c++) {
            float iv[4];
            #pragma unroll
            for (int i = 0; i < 4; i++) iv[i] = st[(pxg * 4 + i) * 65 + c];
            #pragma unroll
            for (int j = 0; j < 4; j++) {
                float wv = ws[c * 64 + ocg * 4 + j];
                #pragma unroll
                for (int i = 0; i < 4; i++) acc[i][j] += iv[i] * wv;
            }
        }
    }
    #pragma unroll
    for (int i = 0; i < 4; i++) {
        int p = pxg * 4 + i;
        int yy = ty0 + (p >> 3), xx = tx0 + (p & 7);
        size_t pg = (size_t)(b * HH + yy) * WWID + xx;
        #pragma unroll
        for (int j = 0; j < 4; j++) {
            int oc = ocg * 4 + j;
            out[pg * 64 + oc] = acc[i][j] + bias[oc];
        }
    }
}

// ---------------- final: (x1+x2) @ w_out^T + b_out + residual x, NCHW out ---
__global__ __launch_bounds__(256) void k_final(
    const float* __restrict__ x1, const float* __restrict__ x2,
    const float* __restrict__ xin, const float* __restrict__ w_out,
    const float* __restrict__ b_out, float* __restrict__ out)
{
    __shared__ float st[64 * 65];
    __shared__ float ws[64 * 64];   // [c][o]
    int tid = threadIdx.x;
    size_t p0 = (size_t)blockIdx.x * 64;
    for (int idx = tid; idx < 4096; idx += 256) {
        int o = idx >> 6, c = idx & 63;
        ws[c * 64 + o] = w_out[idx];
    }
    #pragma unroll
    for (int i = 0; i < 16; i++) {
        int v = i * 256 + tid;
        int p = v >> 6, c = v & 63;
        st[p * 65 + c] = x1[(p0 + p) * 64 + c] + x2[(p0 + p) * 64 + c];
    }
    __syncthreads();
    int pxg = tid >> 4, ocg = tid & 15;
    float acc[4][4] = {};
    #pragma unroll 4
    for (int c = 0; c < 64; c++) {
        float iv[4];
        #pragma unroll
        for (int i = 0; i < 4; i++) iv[i] = st[(pxg * 4 + i) * 65 + c];
        #pragma unroll
        for (int j = 0; j < 4; j++) {
            float wv = ws[c * 64 + ocg * 4 + j];
            #pragma unroll
            for (int i = 0; i < 4; i++) acc[i][j] += iv[i] * wv;
        }
    }
    int b = (int)(p0 / HW);
    int hwbase = (int)(p0 % HW);
    #pragma unroll
    for (int i = 0; i < 4; i++) {
        int hw = hwbase + pxg * 4 + i;
        #pragma unroll
        for (int j = 0; j < 4; j++) {
            int oc = ocg * 4 + j;
            size_t a = ((size_t)b * 64 + oc) * HW + hw;
            out[a] = acc[i][j] + b_out[oc] + xin[a];
        }
    }
}

// ---------------- launch --------------------------------------------------
extern "C" void kernel_launch(void* const* d_in, const int* in_sizes, int n_in,
                              void* d_out, int out_size) {
    const float* x    = (const float*)d_in[0];
    const float* ln_w = (const float*)d_in[1];
    const float* ln_b = (const float*)d_in[2];
    const float* w_in = (const float*)d_in[3];
    const float* b_in = (const float*)d_in[4];
    const float* w_out= (const float*)d_in[5];
    const float* b_out= (const float*)d_in[6];
    const float* dw1  = (const float*)d_in[7];
    const float* db1  = (const float*)d_in[8];
    const float* dw2  = (const float*)d_in[9];
    const float* db2  = (const float*)d_in[10];
    const float* dw3  = (const float*)d_in[11];
    const float* db3  = (const float*)d_in[12];
    const float* ow1  = (const float*)d_in[13];
    const float* ob1  = (const float*)d_in[14];
    const float* ow2  = (const float*)d_in[15];
    const float* ob2  = (const float*)d_in[16];
    const float* ow3  = (const float*)d_in[17];
    const float* ob3  = (const float*)d_in[18];
    float* out = (float*)d_out;

    float *px1, *px2, *py, *poff, *pwA, *pwB;
    cudaGetSymbolAddress((void**)&px1,  g_x1);
    cudaGetSymbolAddress((void**)&px2,  g_x2);
    cudaGetSymbolAddress((void**)&py,   g_y);
    cudaGetSymbolAddress((void**)&poff, g_off);
    cudaGetSymbolAddress((void**)&pwA,  g_wA);
    cudaGetSymbolAddress((void**)&pwB,  g_wB);

    dim3 tiles(WWID / 8, HH / 8, BATCH);

    k_ln_win<<<BHW / 8, 256>>>(x, ln_w, ln_b, w_in, b_in, px1, px2);

    // stage 1: offset conv 5x5 -> 98, deform 7x7
    k_transpose<<<256, 256>>>(ow1, pwA, 25, 98, 112);
    k_conv<5, 2, 98, 112><<<tiles, 256>>>(px1, pwA, ob1, poff);
    k_transpose<<<256, 256>>>(dw1, pwB, 49, 64, 64);
    k_deform<7, 3, 98><<<tiles, 256>>>(px1, poff, pwB, db1, py);

    // stage 2: offset conv 5x5 -> 50, deform 5x5
    k_transpose<<<256, 256>>>(ow2, pwA, 25, 50, 64);
    k_conv<5, 2, 50, 64><<<tiles, 256>>>(py, pwA, ob2, poff);
    k_transpose<<<256, 256>>>(dw2, pwB, 25, 64, 64);
    k_deform<5, 2, 50><<<tiles, 256>>>(py, poff, pwB, db2, px1);

    // stage 3: offset conv 3x3 -> 18, deform 3x3
    k_transpose<<<256, 256>>>(ow3, pwA, 9, 18, 32);
    k_conv<3, 1, 18, 32><<<tiles, 256>>>(px1, pwA, ob3, poff);
    k_transpose<<<256, 256>>>(dw3, pwB, 9, 64, 64);
    k_deform<3, 1, 18><<<tiles, 256>>>(px1, poff, pwB, db3, py);

    k_final<<<BHW / 64, 256>>>(py, px2, x, w_out, b_out, out);
}

// round 2
// speedup vs baseline: 1.3962x; 1.3962x over previous
#include <cuda_runtime.h>
#include <math.h>

#define BATCH 4
#define CH    64
#define HH    192
#define WWID  192
#define HW    (HH*WWID)
#define BHW   (BATCH*HW)
#define SPX   257          // st pixel-stride (odd, 257%32==1 -> conflict-free)

// ---------------- device scratch (allocation-free) ----------------
__device__ float g_x1 [BHW*CH];      // NHWC
__device__ float g_x2 [BHW*CH];      // NHWC
__device__ float g_y  [BHW*CH];      // NHWC ping-pong
__device__ float g_off[98*BHW];      // PLANAR offsets [ch][pixel]
__device__ float g_wA [25*64*112];   // transposed offset-conv weights [tap][c][ocPad]
__device__ float g_wB [49*64*64];    // transposed deform weights     [tap][c][oc]

// ---------------- f32x2 helpers -------------------------------------------
static __device__ __forceinline__ unsigned long long splat2(float x) {
    unsigned long long r;
    asm("mov.b64 %0, {%1, %1};" : "=l"(r) : "f"(x));
    return r;
}
static __device__ __forceinline__ void fma2(unsigned long long& d,
                                            unsigned long long a,
                                            unsigned long long b) {
    asm("fma.rn.f32x2 %0, %1, %2, %0;" : "+l"(d) : "l"(a), "l"(b));
}
static __device__ __forceinline__ float2 unpack2(unsigned long long v) {
    float2 f;
    asm("mov.b64 {%0, %1}, %2;" : "=f"(f.x), "=f"(f.y) : "l"(v));
    return f;
}

// ---------------- weight transpose: w[O][C][K][K] -> out[tap][c][ocPad] ----
__global__ void k_transpose(const float* __restrict__ w, float* __restrict__ out,
                            int K2, int KOUT, int KOUTP) {
    int n = K2 * 64 * KOUTP;
    for (int idx = blockIdx.x * blockDim.x + threadIdx.x; idx < n;
         idx += gridDim.x * blockDim.x) {
        int oc  = idx % KOUTP;
        int c   = (idx / KOUTP) % 64;
        int tap = idx / (KOUTP * 64);
        out[idx] = (oc < KOUT) ? w[(oc * 64 + c) * K2 + tap] : 0.f;
    }
}

// ---------------- fused LayerNorm + 1x1 conv (w_in: 64 -> 128) -------------
__global__ __launch_bounds__(256) void k_ln_win(
    const float* __restrict__ x, const float* __restrict__ ln_w,
    const float* __restrict__ ln_b, const float* __restrict__ w_in,
    const float* __restrict__ b_in, float* __restrict__ out1,
    float* __restrict__ out2)
{
    __shared__ float wT[64 * 128];   // [c][o]
    __shared__ float hb[8][64];
    int tid = threadIdx.x;
    for (int idx = tid; idx < 8192; idx += 256) {
        int o = idx >> 6, c = idx & 63;
        wT[c * 128 + o] = w_in[idx];
    }
    int wp = tid >> 5, lane = tid & 31;
    int pg = blockIdx.x * 8 + wp;
    int b = pg / HW, hw = pg % HW;
    const float* xb = x + (size_t)b * CH * HW + hw;
    float v0 = xb[(size_t)lane * HW];
    float v1 = xb[(size_t)(lane + 32) * HW];
    float s = v0 + v1, q = v0 * v0 + v1 * v1;
    #pragma unroll
    for (int o = 16; o; o >>= 1) {
        s += __shfl_xor_sync(0xffffffffu, s, o);
        q += __shfl_xor_sync(0xffffffffu, q, o);
    }
    float mu  = s * (1.f / 64.f);
    float var = q * (1.f / 64.f) - mu * mu;
    float rs  = rsqrtf(var + 1e-5f);
    hb[wp][lane]      = (v0 - mu) * rs * ln_w[lane]      + ln_b[lane];
    hb[wp][lane + 32] = (v1 - mu) * rs * ln_w[lane + 32] + ln_b[lane + 32];
    __syncthreads();
    float a0 = b_in[lane], a1 = b_in[lane + 32];
    float a2 = b_in[lane + 64], a3 = b_in[lane + 96];
    #pragma unroll 8
    for (int c = 0; c < 64; c++) {
        float hv = hb[wp][c];
        const float* wr = &wT[c * 128 + lane];
        a0 += hv * wr[0];  a1 += hv * wr[32];
        a2 += hv * wr[64]; a3 += hv * wr[96];
    }
    float* o1 = out1 + (size_t)pg * 64;
    float* o2 = out2 + (size_t)pg * 64;
    o1[lane] = a0; o1[lane + 32] = a1;
    o2[lane] = a2; o2[lane + 32] = a3;
}

// ---------------- dense KxK conv (offset predictor), NHWC in, PLANAR out ---
// 16x16 px tile. 256 thr = 8 warps (oc groups) x 32 lanes (px). f32x2 math.
template<int K, int PAD, int KOUT, int KOUTP, int OCT, int OCB>
__global__ __launch_bounds__(256) void k_conv(
    const float* __restrict__ in, const float* __restrict__ wT,
    const float* __restrict__ bias, float* __restrict__ out)
{
    extern __shared__ float sm[];
    float* st = sm;                 // [64][SPX] transposed tile
    float* ws = sm + 64 * SPX;      // [64][KOUTP]
    constexpr int NP = OCT / 2;
    int tid = threadIdx.x, lane = tid & 31, w = tid >> 5;
    int b   = blockIdx.z;
    int ty0 = blockIdx.y * 16, tx0 = blockIdx.x * 16;

    unsigned long long acc[8][NP];
    #pragma unroll
    for (int i = 0; i < 8; i++)
        #pragma unroll
        for (int j = 0; j < NP; j++) acc[i][j] = 0ull;

    for (int tap = 0; tap < K * K; tap++) {
        int ki = tap / K, kj = tap % K;
        __syncthreads();
        // weights slice [64][KOUTP]
        {
            const float4* src = (const float4*)(wT + (size_t)tap * 64 * KOUTP);
            float4* dst = (float4*)ws;
            for (int idx = tid; idx < 64 * KOUTP / 4; idx += 256) dst[idx] = src[idx];
        }
        // shifted tile -> st[c][px]
        #pragma unroll 4
        for (int it = 0; it < 32; it++) {
            int v  = it * 256 + tid;
            int p  = v >> 5, c2 = v & 31;
            int yy = ty0 + (p >> 4) + ki - PAD;
            int xx = tx0 + (p & 15) + kj - PAD;
            float2 val = make_float2(0.f, 0.f);
            if (yy >= 0 && yy < HH && xx >= 0 && xx < WWID)
                val = *(const float2*)(in + ((size_t)((b * HH + yy) * WWID + xx)) * 64 + 2 * c2);
            st[(2 * c2)     * SPX + p] = val.x;
            st[(2 * c2 + 1) * SPX + p] = val.y;
        }
        __syncthreads();
        // GEMM
        #pragma unroll 8
        for (int c = 0; c < 64; c++) {
            unsigned long long iv2[8];
            #pragma unroll
            for (int i = 0; i < 8; i++) iv2[i] = splat2(st[c * SPX + lane + 32 * i]);
            const float* wrow = ws + c * KOUTP + OCB + w * OCT;
            #pragma unroll
            for (int j = 0; j < NP; j++) {
                unsigned long long wv = *(const unsigned long long*)(wrow + 2 * j);
                #pragma unroll
                for (int i = 0; i < 8; i++) fma2(acc[i][j], iv2[i], wv);
            }
        }
    }
    // store PLANAR [oc][pixel] with bias
    #pragma unroll
    for (int i = 0; i < 8; i++) {
        int p  = lane + 32 * i;
        int pg = (b * HH + ty0 + (p >> 4)) * WWID + tx0 + (p & 15);
        #pragma unroll
        for (int j = 0; j < NP; j++) {
            float2 v = unpack2(acc[i][j]);
            int oc = OCB + w * OCT + 2 * j;
            if (oc     < KOUT) out[(size_t)oc       * BHW + pg] = v.x + bias[oc];
            if (oc + 1 < KOUT) out[(size_t)(oc + 1) * BHW + pg] = v.y + bias[oc + 1];
        }
    }
}

// ---------------- deformable KxK conv (Cout=64), NHWC in/out ----------------
template<int K, int PAD>
__global__ __launch_bounds__(256) void k_deform(
    const float* __restrict__ in, const float* __restrict__ off,
    const float* __restrict__ wT, const float* __restrict__ bias,
    float* __restrict__ out)
{
    extern __shared__ float sm[];
    float* st  = sm;                    // [64][SPX]
    float* ws  = sm + 64 * SPX;         // [64][64]
    float* w00 = ws + 4096;             // 4 x 256 bilinear weights
    float* w01 = w00 + 256;
    float* w10 = w01 + 256;
    float* w11 = w10 + 256;
    int*   s_y0 = (int*)(w11 + 256);
    int*   s_x0 = s_y0 + 256;

    int tid = threadIdx.x, lane = tid & 31, w = tid >> 5;
    int b   = blockIdx.z;
    int ty0 = blockIdx.y * 16, tx0 = blockIdx.x * 16;
    const float* base = in + (size_t)b * HW * 64;

    unsigned long long acc[8][4];
    #pragma unroll
    for (int i = 0; i < 8; i++)
        #pragma unroll
        for (int j = 0; j < 4; j++) acc[i][j] = 0ull;

    for (int tap = 0; tap < K * K; tap++) {
        int ki = tap / K, kj = tap % K;
        __syncthreads();
        // weights slice
        {
            const float4* src = (const float4*)(wT + (size_t)tap * 4096);
            float4* dst = (float4*)ws;
            for (int idx = tid; idx < 1024; idx += 256) dst[idx] = src[idx];
        }
        // per-pixel sampling params (planar offsets -> coalesced)
        {
            int p  = tid;
            int yy = ty0 + (p >> 4), xx = tx0 + (p & 15);
            int pg = (b * HH + yy) * WWID + xx;
            float oy = off[(size_t)(2 * tap)     * BHW + pg];
            float ox = off[(size_t)(2 * tap + 1) * BHW + pg];
            float py = (float)(yy + ki - PAD) + oy;
            float px = (float)(xx + kj - PAD) + ox;
            float fy = floorf(py), fx = floorf(px);
            float wy = py - fy,    wx = px - fx;
            s_y0[p] = (int)fy; s_x0[p] = (int)fx;
            w00[p] = (1.f - wy) * (1.f - wx);
            w01[p] = (1.f - wy) * wx;
            w10[p] = wy * (1.f - wx);
            w11[p] = wy * wx;
        }
        __syncthreads();
        // bilinear sampling -> st[c][px]
        #pragma unroll 4
        for (int it = 0; it < 32; it++) {
            int v  = it * 256 + tid;
            int p  = v >> 5, c2 = v & 31;
            int y0 = s_y0[p], x0 = s_x0[p];
            float a00 = w00[p], a01 = w01[p], a10 = w10[p], a11 = w11[p];
            bool yv0 = (unsigned)y0       < HH;
            bool yv1 = (unsigned)(y0 + 1) < HH;
            bool xv0 = (unsigned)x0       < WWID;
            bool xv1 = (unsigned)(x0 + 1) < WWID;
            long long r0 = ((long long)y0 * WWID + x0) * 64 + 2 * c2;
            float2 v00 = make_float2(0.f, 0.f), v01 = v00, v10 = v00, v11 = v00;
            if (yv0 && xv0) v00 = *(const float2*)(base + r0);
            if (yv0 && xv1) v01 = *(const float2*)(base + r0 + 64);
            if (yv1 && xv0) v10 = *(const float2*)(base + r0 + 64 * WWID);
            if (yv1 && xv1) v11 = *(const float2*)(base + r0 + 64 * WWID + 64);
            float rx = a00 * v00.x + a01 * v01.x + a10 * v10.x + a11 * v11.x;
            float ry = a00 * v00.y + a01 * v01.y + a10 * v10.y + a11 * v11.y;
            st[(2 * c2)     * SPX + p] = rx;
            st[(2 * c2 + 1) * SPX + p] = ry;
        }
        __syncthreads();
        // GEMM 64c x 64oc
        #pragma unroll 8
        for (int c = 0; c < 64; c++) {
            unsigned long long iv2[8];
            #pragma unroll
            for (int i = 0; i < 8; i++) iv2[i] = splat2(st[c * SPX + lane + 32 * i]);
            const float* wrow = ws + c * 64 + w * 8;
            #pragma unroll
            for (int j = 0; j < 4; j++) {
                unsigned long long wv = *(const unsigned long long*)(wrow + 2 * j);
                #pragma unroll
                for (int i = 0; i < 8; i++) fma2(acc[i][j], iv2[i], wv);
            }
        }
    }
    // store NHWC with bias
    #pragma unroll
    for (int i = 0; i < 8; i++) {
        int p  = lane + 32 * i;
        int pg = (b * HH + ty0 + (p >> 4)) * WWID + tx0 + (p & 15);
        float* op = out + (size_t)pg * 64 + w * 8;
        #pragma unroll
        for (int j = 0; j < 4; j++) {
            float2 v = unpack2(acc[i][j]);
            int oc = w * 8 + 2 * j;
            op[2 * j]     = v.x + bias[oc];
            op[2 * j + 1] = v.y + bias[oc + 1];
        }
    }
}

// ---------------- final: (x1+x2) @ w_out^T + b_out + residual x, NCHW out ---
__global__ __launch_bounds__(256) void k_final(
    const float* __restrict__ x1, const float* __restrict__ x2,
    const float* __restrict__ xin, const float* __restrict__ w_out,
    const float* __restrict__ b_out, float* __restrict__ out)
{
    __shared__ float st[64 * 65];
    __shared__ float ws[64 * 64];   // [c][o]
    int tid = threadIdx.x;
    size_t p0 = (size_t)blockIdx.x * 64;
    for (int idx = tid; idx < 4096; idx += 256) {
        int o = idx >> 6, c = idx & 63;
        ws[c * 64 + o] = w_out[idx];
    }
    #pragma unroll
    for (int i = 0; i < 16; i++) {
        int v = i * 256 + tid;
        int p = v >> 6, c = v & 63;
        st[p * 65 + c] = x1[(p0 + p) * 64 + c] + x2[(p0 + p) * 64 + c];
    }
    __syncthreads();
    int pxg = tid >> 4, ocg = tid & 15;
    float acc[4][4] = {};
    #pragma unroll 4
    for (int c = 0; c < 64; c++) {
        float iv[4];
        #pragma unroll
        for (int i = 0; i < 4; i++) iv[i] = st[(pxg * 4 + i) * 65 + c];
        #pragma unroll
        for (int j = 0; j < 4; j++) {
            float wv = ws[c * 64 + ocg * 4 + j];
            #pragma unroll
            for (int i = 0; i < 4; i++) acc[i][j] += iv[i] * wv;
        }
    }
    int b = (int)(p0 / HW);
    int hwbase = (int)(p0 % HW);
    #pragma unroll
    for (int i = 0; i < 4; i++) {
        int hw = hwbase + pxg * 4 + i;
        #pragma unroll
        for (int j = 0; j < 4; j++) {
            int oc = ocg * 4 + j;
            size_t a = ((size_t)b * 64 + oc) * HW + hw;
            out[a] = acc[i][j] + b_out[oc] + xin[a];
        }
    }
}

// ---------------- launch --------------------------------------------------
extern "C" void kernel_launch(void* const* d_in, const int* in_sizes, int n_in,
                              void* d_out, int out_size) {
    const float* x    = (const float*)d_in[0];
    const float* ln_w = (const float*)d_in[1];
    const float* ln_b = (const float*)d_in[2];
    const float* w_in = (const float*)d_in[3];
    const float* b_in = (const float*)d_in[4];
    const float* w_out= (const float*)d_in[5];
    const float* b_out= (const float*)d_in[6];
    const float* dw1  = (const float*)d_in[7];
    const float* db1  = (const float*)d_in[8];
    const float* dw2  = (const float*)d_in[9];
    const float* db2  = (const float*)d_in[10];
    const float* dw3  = (const float*)d_in[11];
    const float* db3  = (const float*)d_in[12];
    const float* ow1  = (const float*)d_in[13];
    const float* ob1  = (const float*)d_in[14];
    const float* ow2  = (const float*)d_in[15];
    const float* ob2  = (const float*)d_in[16];
    const float* ow3  = (const float*)d_in[17];
    const float* ob3  = (const float*)d_in[18];
    float* out = (float*)d_out;

    float *px1, *px2, *py, *poff, *pwA, *pwB;
    cudaGetSymbolAddress((void**)&px1,  g_x1);
    cudaGetSymbolAddress((void**)&px2,  g_x2);
    cudaGetSymbolAddress((void**)&py,   g_y);
    cudaGetSymbolAddress((void**)&poff, g_off);
    cudaGetSymbolAddress((void**)&pwA,  g_wA);
    cudaGetSymbolAddress((void**)&pwB,  g_wB);

    const int SM112 = (64 * SPX + 64 * 112) * 4;
    const int SM64  = (64 * SPX + 64 * 64)  * 4;
    const int SM32  = (64 * SPX + 64 * 32)  * 4;
    const int SMD   = (64 * SPX + 4096 + 1024 + 512) * 4;

    cudaFuncSetAttribute(k_conv<5,2,98,112,8,0>,  cudaFuncAttributeMaxDynamicSharedMemorySize, SM112);
    cudaFuncSetAttribute(k_conv<5,2,98,112,6,64>, cudaFuncAttributeMaxDynamicSharedMemorySize, SM112);
    cudaFuncSetAttribute(k_conv<5,2,50,64,8,0>,   cudaFuncAttributeMaxDynamicSharedMemorySize, SM64);
    cudaFuncSetAttribute(k_conv<3,1,18,32,4,0>,   cudaFuncAttributeMaxDynamicSharedMemorySize, SM32);
    cudaFuncSetAttribute(k_deform<7,3>, cudaFuncAttributeMaxDynamicSharedMemorySize, SMD);
    cudaFuncSetAttribute(k_deform<5,2>, cudaFuncAttributeMaxDynamicSharedMemorySize, SMD);
    cudaFuncSetAttribute(k_deform<3,1>, cudaFuncAttributeMaxDynamicSharedMemorySize, SMD);

    dim3 tiles(WWID / 16, HH / 16, BATCH);

    k_ln_win<<<BHW / 8, 256>>>(x, ln_w, ln_b, w_in, b_in, px1, px2);

    // stage 1: offset conv 5x5 -> 98, deform 7x7
    k_transpose<<<256, 256>>>(ow1, pwA, 25, 98, 112);
    k_conv<5,2,98,112,8,0> <<<tiles, 256, SM112>>>(px1, pwA, ob1, poff);
    k_conv<5,2,98,112,6,64><<<tiles, 256, SM112>>>(px1, pwA, ob1, poff);
    k_transpose<<<256, 256>>>(dw1, pwB, 49, 64, 64);
    k_deform<7,3><<<tiles, 256, SMD>>>(px1, poff, pwB, db1, py);

    // stage 2: offset conv 5x5 -> 50, deform 5x5
    k_transpose<<<256, 256>>>(ow2, pwA, 25, 50, 64);
    k_conv<5,2,50,64,8,0><<<tiles, 256, SM64>>>(py, pwA, ob2, poff);
    k_transpose<<<256, 256>>>(dw2, pwB, 25, 64, 64);
    k_deform<5,2><<<tiles, 256, SMD>>>(py, poff, pwB, db2, px1);

    // stage 3: offset conv 3x3 -> 18, deform 3x3
    k_transpose<<<256, 256>>>(ow3, pwA, 9, 18, 32);
    k_conv<3,1,18,32,4,0><<<tiles, 256, SM32>>>(px1, pwA, ob3, poff);
    k_transpose<<<256, 256>>>(dw3, pwB, 9, 64, 64);
    k_deform<3,1><<<tiles, 256, SMD>>>(px1, poff, pwB, db3, py);

    k_final<<<BHW / 64, 256>>>(py, px2, x, w_out, b_out, out);
}

// round 3
// speedup vs baseline: 2.3028x; 1.6493x over previous
#include <cuda_runtime.h>
#include <math.h>
#include <stdint.h>

#define BATCH 4
#define CH    64
#define HH    192
#define WWID  192
#define HW    (HH*WWID)
#define BHW   (BATCH*HW)
#define ASTR  68           // A smem stride (words): 68%32==4 -> conflict-free frags

// ---------------- device scratch (allocation-free) ----------------
__device__ float g_x1 [BHW*CH];       // NHWC
__device__ float g_x2 [BHW*CH];       // NHWC
__device__ float g_y  [BHW*CH];       // NHWC ping-pong
__device__ float g_off[98*BHW];       // PLANAR offsets [ch][pixel]
__device__ float g_wA [25*64*128];    // transposed offset-conv weights [tap][c][ocPad]
__device__ float g_wB [49*64*64];     // transposed deform weights     [tap][c][oc]

// ---------------- tf32 helpers --------------------------------------------
static __device__ __forceinline__ uint32_t to_tf32(float f) {
    uint32_t u;
    asm("cvt.rna.tf32.f32 %0, %1;" : "=r"(u) : "f"(f));
    return u;
}
static __device__ __forceinline__ void mma_tf32(float* d, const uint32_t* a,
                                                const uint32_t* b) {
    asm volatile(
        "mma.sync.aligned.m16n8k8.row.col.f32.tf32.tf32.f32 "
        "{%0,%1,%2,%3},{%4,%5,%6,%7},{%8,%9},{%0,%1,%2,%3};"
        : "+f"(d[0]), "+f"(d[1]), "+f"(d[2]), "+f"(d[3])
        : "r"(a[0]), "r"(a[1]), "r"(a[2]), "r"(a[3]), "r"(b[0]), "r"(b[1]));
}

// ---------------- weight transpose: w[O][C][K][K] -> out[tap][c][ocPad] ----
__global__ void k_transpose(const float* __restrict__ w, float* __restrict__ out,
                            int K2, int KOUT, int KOUTP) {
    int n = K2 * 64 * KOUTP;
    for (int idx = blockIdx.x * blockDim.x + threadIdx.x; idx < n;
         idx += gridDim.x * blockDim.x) {
        int oc  = idx % KOUTP;
        int c   = (idx / KOUTP) % 64;
        int tap = idx / (KOUTP * 64);
        out[idx] = (oc < KOUT) ? w[(oc * 64 + c) * K2 + tap] : 0.f;
    }
}

// ---------------- fused LayerNorm + 1x1 conv (w_in: 64 -> 128) -------------
__global__ __launch_bounds__(256) void k_ln_win(
    const float* __restrict__ x, const float* __restrict__ ln_w,
    const float* __restrict__ ln_b, const float* __restrict__ w_in,
    const float* __restrict__ b_in, float* __restrict__ out1,
    float* __restrict__ out2)
{
    __shared__ float wT[64 * 128];   // [c][o]
    __shared__ float hb[8][64];
    int tid = threadIdx.x;
    for (int idx = tid; idx < 8192; idx += 256) {
        int o = idx >> 6, c = idx & 63;
        wT[c * 128 + o] = w_in[idx];
    }
    int wp = tid >> 5, lane = tid & 31;
    int pg = blockIdx.x * 8 + wp;
    int b = pg / HW, hw = pg % HW;
    const float* xb = x + (size_t)b * CH * HW + hw;
    float v0 = xb[(size_t)lane * HW];
    float v1 = xb[(size_t)(lane + 32) * HW];
    float s = v0 + v1, q = v0 * v0 + v1 * v1;
    #pragma unroll
    for (int o = 16; o; o >>= 1) {
        s += __shfl_xor_sync(0xffffffffu, s, o);
        q += __shfl_xor_sync(0xffffffffu, q, o);
    }
    float mu  = s * (1.f / 64.f);
    float var = q * (1.f / 64.f) - mu * mu;
    float rs  = rsqrtf(var + 1e-5f);
    hb[wp][lane]      = (v0 - mu) * rs * ln_w[lane]      + ln_b[lane];
    hb[wp][lane + 32] = (v1 - mu) * rs * ln_w[lane + 32] + ln_b[lane + 32];
    __syncthreads();
    float a0 = b_in[lane], a1 = b_in[lane + 32];
    float a2 = b_in[lane + 64], a3 = b_in[lane + 96];
    #pragma unroll 8
    for (int c = 0; c < 64; c++) {
        float hv = hb[wp][c];
        const float* wr = &wT[c * 128 + lane];
        a0 += hv * wr[0];  a1 += hv * wr[32];
        a2 += hv * wr[64]; a3 += hv * wr[96];
    }
    float* o1 = out1 + (size_t)pg * 64;
    float* o2 = out2 + (size_t)pg * 64;
    o1[lane] = a0; o1[lane + 32] = a1;
    o2[lane] = a2; o2[lane + 32] = a3;
}

// ---------------- dense KxK conv (offset predictor), tf32 MMA ---------------
// 16x8 px tile (128 px), 8 warps = 4 pxg x 2 ocg. SPAN oc per launch.
template<int K, int PAD, int KOUT, int KOUTP, int SPAN, int OCB>
__global__ __launch_bounds__(256) void k_conv_tc(
    const float* __restrict__ in, const float* __restrict__ wT,
    const float* __restrict__ bias, float* __restrict__ out)
{
    constexpr int NT   = SPAN / 16;     // n8 tiles per oc-group
    constexpr int BSTR = SPAN + 4;
    extern __shared__ uint32_t sm[];
    uint32_t* As = sm;                  // [128][ASTR]
    uint32_t* Bs = sm + 128 * ASTR;     // [64][BSTR]
    int tid = threadIdx.x, lane = tid & 31, w = tid >> 5;
    int q = lane >> 2, r = lane & 3;
    int pxg = w >> 1, ocg = w & 1;
    int b = blockIdx.z;
    int ty0 = blockIdx.y * 8, tx0 = blockIdx.x * 16;
    float acc[2][NT][4] = {};

    for (int tap = 0; tap < K * K; tap++) {
        int ki = tap / K, kj = tap % K;
        __syncthreads();
        for (int idx = tid; idx < 64 * SPAN; idx += 256) {
            int c = idx / SPAN, ocl = idx % SPAN;
            Bs[c * BSTR + ocl] =
                to_tf32(wT[(size_t)tap * 64 * KOUTP + c * KOUTP + OCB + ocl]);
        }
        #pragma unroll 4
        for (int it = 0; it < 16; it++) {
            int v = it * 256 + tid;
            int p = v >> 5, c2 = v & 31;
            int yy = ty0 + (p >> 4) + ki - PAD;
            int xx = tx0 + (p & 15) + kj - PAD;
            float2 val = make_float2(0.f, 0.f);
            if (yy >= 0 && yy < HH && xx >= 0 && xx < WWID)
                val = *(const float2*)(in + ((size_t)((b * HH + yy) * WWID + xx)) * 64 + 2 * c2);
            uint32_t* d = As + p * ASTR + 2 * c2;
            d[0] = to_tf32(val.x); d[1] = to_tf32(val.y);
        }
        __syncthreads();
        #pragma unroll
        for (int kc = 0; kc < 8; kc++) {
            uint32_t a[2][4];
            #pragma unroll
            for (int m = 0; m < 2; m++) {
                int pr = pxg * 32 + m * 16;
                a[m][0] = As[(pr + q)     * ASTR + kc * 8 + r];
                a[m][1] = As[(pr + q + 8) * ASTR + kc * 8 + r];
                a[m][2] = As[(pr + q)     * ASTR + kc * 8 + r + 4];
                a[m][3] = As[(pr + q + 8) * ASTR + kc * 8 + r + 4];
            }
            #pragma unroll
            for (int nt = 0; nt < NT; nt++) {
                uint32_t bb[2];
                int ocb = ocg * (SPAN / 2) + nt * 8 + q;
                bb[0] = Bs[(kc * 8 + r)     * BSTR + ocb];
                bb[1] = Bs[(kc * 8 + r + 4) * BSTR + ocb];
                mma_tf32(acc[0][nt], a[0], bb);
                mma_tf32(acc[1][nt], a[1], bb);
            }
        }
    }
    #pragma unroll
    for (int m = 0; m < 2; m++) {
        #pragma unroll
        for (int nt = 0; nt < NT; nt++) {
            #pragma unroll
            for (int hh = 0; hh < 2; hh++) {
                int p  = pxg * 32 + m * 16 + q + hh * 8;
                int pg = (b * HH + ty0 + (p >> 4)) * WWID + tx0 + (p & 15);
                int oc = OCB + ocg * (SPAN / 2) + nt * 8 + 2 * r;
                float v0 = acc[m][nt][hh * 2 + 0];
                float v1 = acc[m][nt][hh * 2 + 1];
                if (oc     < KOUT) out[(size_t)oc       * BHW + pg] = v0 + bias[oc];
                if (oc + 1 < KOUT) out[(size_t)(oc + 1) * BHW + pg] = v1 + bias[oc + 1];
            }
        }
    }
}

// ---------------- deformable KxK conv (Cout=64), tf32 MMA -------------------
template<int K, int PAD>
__global__ __launch_bounds__(256) void k_deform_tc(
    const float* __restrict__ in, const float* __restrict__ off,
    const float* __restrict__ wT, const float* __restrict__ bias,
    float* __restrict__ out)
{
    constexpr int BSTR = 68;
    extern __shared__ uint32_t sm[];
    uint32_t* As = sm;                       // [128][ASTR]
    uint32_t* Bs = sm + 128 * ASTR;          // [64][BSTR]
    float* w00 = (float*)(Bs + 64 * BSTR);   // 4 x 128 bilinear weights
    float* w01 = w00 + 128;
    float* w10 = w01 + 128;
    float* w11 = w10 + 128;
    int*   s_y0 = (int*)(w11 + 128);
    int*   s_x0 = s_y0 + 128;

    int tid = threadIdx.x, lane = tid & 31, w = tid >> 5;
    int q = lane >> 2, r = lane & 3;
    int pxg = w >> 1, ocg = w & 1;
    int b = blockIdx.z;
    int ty0 = blockIdx.y * 8, tx0 = blockIdx.x * 16;
    const float* base = in + (size_t)b * HW * 64;
    float acc[2][4][4] = {};

    for (int tap = 0; tap < K * K; tap++) {
        int ki = tap / K, kj = tap % K;
        __syncthreads();
        for (int idx = tid; idx < 4096; idx += 256) {
            int c = idx >> 6, ocl = idx & 63;
            Bs[c * BSTR + ocl] = to_tf32(wT[(size_t)tap * 4096 + c * 64 + ocl]);
        }
        if (tid < 128) {
            int p  = tid;
            int yy = ty0 + (p >> 4), xx = tx0 + (p & 15);
            int pg = (b * HH + yy) * WWID + xx;
            float oy = off[(size_t)(2 * tap)     * BHW + pg];
            float ox = off[(size_t)(2 * tap + 1) * BHW + pg];
            float py = (float)(yy + ki - PAD) + oy;
            float px = (float)(xx + kj - PAD) + ox;
            float fy = floorf(py), fx = floorf(px);
            float wy = py - fy,    wx = px - fx;
            s_y0[p] = (int)fy; s_x0[p] = (int)fx;
            w00[p] = (1.f - wy) * (1.f - wx);
            w01[p] = (1.f - wy) * wx;
            w10[p] = wy * (1.f - wx);
            w11[p] = wy * wx;
        }
        __syncthreads();
        #pragma unroll 4
        for (int it = 0; it < 16; it++) {
            int v  = it * 256 + tid;
            int p  = v >> 5, c2 = v & 31;
            int y0 = s_y0[p], x0 = s_x0[p];
            float a00 = w00[p], a01 = w01[p], a10 = w10[p], a11 = w11[p];
            bool yv0 = (unsigned)y0       < HH;
            bool yv1 = (unsigned)(y0 + 1) < HH;
            bool xv0 = (unsigned)x0       < WWID;
            bool xv1 = (unsigned)(x0 + 1) < WWID;
            long long r0 = ((long long)y0 * WWID + x0) * 64 + 2 * c2;
            float2 v00 = make_float2(0.f, 0.f), v01 = v00, v10 = v00, v11 = v00;
            if (yv0 && xv0) v00 = *(const float2*)(base + r0);
            if (yv0 && xv1) v01 = *(const float2*)(base + r0 + 64);
            if (yv1 && xv0) v10 = *(const float2*)(base + r0 + 64 * WWID);
            if (yv1 && xv1) v11 = *(const float2*)(base + r0 + 64 * WWID + 64);
            float rx = a00 * v00.x + a01 * v01.x + a10 * v10.x + a11 * v11.x;
            float ry = a00 * v00.y + a01 * v01.y + a10 * v10.y + a11 * v11.y;
            uint32_t* d = As + p * ASTR + 2 * c2;
            d[0] = to_tf32(rx); d[1] = to_tf32(ry);
        }
        __syncthreads();
        #pragma unroll
        for (int kc = 0; kc < 8; kc++) {
            uint32_t a[2][4];
            #pragma unroll
            for (int m = 0; m < 2; m++) {
                int pr = pxg * 32 + m * 16;
                a[m][0] = As[(pr + q)     * ASTR + kc * 8 + r];
                a[m][1] = As[(pr + q + 8) * ASTR + kc * 8 + r];
                a[m][2] = As[(pr + q)     * ASTR + kc * 8 + r + 4];
                a[m][3] = As[(pr + q + 8) * ASTR + kc * 8 + r + 4];
            }
            #pragma unroll
            for (int nt = 0; nt < 4; nt++) {
                uint32_t bb[2];
                int ocb = ocg * 32 + nt * 8 + q;
                bb[0] = Bs[(kc * 8 + r)     * BSTR + ocb];
                bb[1] = Bs[(kc * 8 + r + 4) * BSTR + ocb];
                mma_tf32(acc[0][nt], a[0], bb);
                mma_tf32(acc[1][nt], a[1], bb);
            }
        }
    }
    #pragma unroll
    for (int m = 0; m < 2; m++) {
        #pragma unroll
        for (int nt = 0; nt < 4; nt++) {
            #pragma unroll
            for (int hh = 0; hh < 2; hh++) {
                int p  = pxg * 32 + m * 16 + q + hh * 8;
                int pg = (b * HH + ty0 + (p >> 4)) * WWID + tx0 + (p & 15);
                int oc = ocg * 32 + nt * 8 + 2 * r;
                float2 v;
                v.x = acc[m][nt][hh * 2 + 0] + bias[oc];
                v.y = acc[m][nt][hh * 2 + 1] + bias[oc + 1];
                *(float2*)(out + (size_t)pg * 64 + oc) = v;
            }
        }
    }
}

// ---------------- final: (x1+x2) @ w_out^T + b_out + residual x, NCHW out ---
__global__ __launch_bounds__(256) void k_final(
    const float* __restrict__ x1, const float* __restrict__ x2,
    const float* __restrict__ xin, const float* __restrict__ w_out,
    const float* __restrict__ b_out, float* __restrict__ out)
{
    __shared__ float st[64 * 65];
    __shared__ float ws[64 * 64];   // [c][o]
    int tid = threadIdx.x;
    size_t p0 = (size_t)blockIdx.x * 64;
    for (int idx = tid; idx < 4096; idx += 256) {
        int o = idx >> 6, c = idx & 63;
        ws[c * 64 + o] = w_out[idx];
    }
    #pragma unroll
    for (int i = 0; i < 16; i++) {
        int v = i * 256 + tid;
        int p = v >> 6, c = v & 63;
        st[p * 65 + c] = x1[(p0 + p) * 64 + c] + x2[(p0 + p) * 64 + c];
    }
    __syncthreads();
    int pxg = tid >> 4, ocg = tid & 15;
    float acc[4][4] = {};
    #pragma unroll 4
    for (int c = 0; c < 64; c++) {
        float iv[4];
        #pragma unroll
        for (int i = 0; i < 4; i++) iv[i] = st[(pxg * 4 + i) * 65 + c];
        #pragma unroll
        for (int j = 0; j < 4; j++) {
            float wv = ws[c * 64 + ocg * 4 + j];
            #pragma unroll
            for (int i = 0; i < 4; i++) acc[i][j] += iv[i] * wv;
        }
    }
    int b = (int)(p0 / HW);
    int hwbase = (int)(p0 % HW);
    #pragma unroll
    for (int i = 0; i < 4; i++) {
        int hw = hwbase + pxg * 4 + i;
        #pragma unroll
        for (int j = 0; j < 4; j++) {
            int oc = ocg * 4 + j;
            size_t a = ((size_t)b * 64 + oc) * HW + hw;
            out[a] = acc[i][j] + b_out[oc] + xin[a];
        }
    }
}

// ---------------- launch --------------------------------------------------
extern "C" void kernel_launch(void* const* d_in, const int* in_sizes, int n_in,
                              void* d_out, int out_size) {
    const float* x    = (const float*)d_in[0];
    const float* ln_w = (const float*)d_in[1];
    const float* ln_b = (const float*)d_in[2];
    const float* w_in = (const float*)d_in[3];
    const float* b_in = (const float*)d_in[4];
    const float* w_out= (const float*)d_in[5];
    const float* b_out= (const float*)d_in[6];
    const float* dw1  = (const float*)d_in[7];
    const float* db1  = (const float*)d_in[8];
    const float* dw2  = (const float*)d_in[9];
    const float* db2  = (const float*)d_in[10];
    const float* dw3  = (const float*)d_in[11];
    const float* db3  = (const float*)d_in[12];
    const float* ow1  = (const float*)d_in[13];
    const float* ob1  = (const float*)d_in[14];
    const float* ow2  = (const float*)d_in[15];
    const float* ob2  = (const float*)d_in[16];
    const float* ow3  = (const float*)d_in[17];
    const float* ob3  = (const float*)d_in[18];
    float* out = (float*)d_out;

    float *px1, *px2, *py, *poff, *pwA, *pwB;
    cudaGetSymbolAddress((void**)&px1,  g_x1);
    cudaGetSymbolAddress((void**)&px2,  g_x2);
    cudaGetSymbolAddress((void**)&py,   g_y);
    cudaGetSymbolAddress((void**)&poff, g_off);
    cudaGetSymbolAddress((void**)&pwA,  g_wA);
    cudaGetSymbolAddress((void**)&pwB,  g_wB);

    const int SMC64 = (128 * ASTR + 64 * 68) * 4;
    const int SMC32 = (128 * ASTR + 64 * 36) * 4;
    const int SMD   = (128 * ASTR + 64 * 68) * 4 + 128 * 6 * 4;

    cudaFuncSetAttribute(k_conv_tc<5,2,98,128,64,0>,  cudaFuncAttributeMaxDynamicSharedMemorySize, SMC64);
    cudaFuncSetAttribute(k_conv_tc<5,2,98,128,64,64>, cudaFuncAttributeMaxDynamicSharedMemorySize, SMC64);
    cudaFuncSetAttribute(k_conv_tc<5,2,50,64,64,0>,   cudaFuncAttributeMaxDynamicSharedMemorySize, SMC64);
    cudaFuncSetAttribute(k_conv_tc<3,1,18,32,32,0>,   cudaFuncAttributeMaxDynamicSharedMemorySize, SMC32);
    cudaFuncSetAttribute(k_deform_tc<7,3>, cudaFuncAttributeMaxDynamicSharedMemorySize, SMD);
    cudaFuncSetAttribute(k_deform_tc<5,2>, cudaFuncAttributeMaxDynamicSharedMemorySize, SMD);
    cudaFuncSetAttribute(k_deform_tc<3,1>, cudaFuncAttributeMaxDynamicSharedMemorySize, SMD);

    dim3 tiles(WWID / 16, HH / 8, BATCH);   // 16x8 px tiles

    k_ln_win<<<BHW / 8, 256>>>(x, ln_w, ln_b, w_in, b_in, px1, px2);

    // stage 1: offset conv 5x5 -> 98, deform 7x7
    k_transpose<<<256, 256>>>(ow1, pwA, 25, 98, 128);
    k_conv_tc<5,2,98,128,64,0>  <<<tiles, 256, SMC64>>>(px1, pwA, ob1, poff);
    k_conv_tc<5,2,98,128,64,64> <<<tiles, 256, SMC64>>>(px1, pwA, ob1, poff);
    k_transpose<<<256, 256>>>(dw1, pwB, 49, 64, 64);
    k_deform_tc<7,3><<<tiles, 256, SMD>>>(px1, poff, pwB, db1, py);

    // stage 2: offset conv 5x5 -> 50, deform 5x5
    k_transpose<<<256, 256>>>(ow2, pwA, 25, 50, 64);
    k_conv_tc<5,2,50,64,64,0><<<tiles, 256, SMC64>>>(py, pwA, ob2, poff);
    k_transpose<<<256, 256>>>(dw2, pwB, 25, 64, 64);
    k_deform_tc<5,2><<<tiles, 256, SMD>>>(py, poff, pwB, db2, px1);

    // stage 3: offset conv 3x3 -> 18, deform 3x3
    k_transpose<<<256, 256>>>(ow3, pwA, 9, 18, 32);
    k_conv_tc<3,1,18,32,32,0><<<tiles, 256, SMC32>>>(px1, pwA, ob3, poff);
    k_transpose<<<256, 256>>>(dw3, pwB, 9, 64, 64);
    k_deform_tc<3,1><<<tiles, 256, SMD>>>(px1, poff, pwB, db3, py);

    k_final<<<BHW / 64, 256>>>(py, px2, x, w_out, b_out, out);
}

// round 4
// speedup vs baseline: 3.2856x; 1.4268x over previous
#include <cuda_runtime.h>
#include <cuda_bf16.h>
#include <math.h>
#include <stdint.h>

#define BATCH 4
#define CH    64
#define HH    192
#define WWID  192
#define HW    (HH*WWID)
#define BHW   (BATCH*HW)

// ---------------- device scratch (allocation-free) ----------------
__device__ float g_x1 [BHW*CH];       // NHWC
__device__ float g_x2 [BHW*CH];       // NHWC
__device__ float g_y  [BHW*CH];       // NHWC ping-pong
__device__ float g_off[98*BHW];       // PLANAR offsets [ch][pixel]
__device__ float g_wA [25*64*128];    // transposed offset-conv weights [tap][c][ocPad]
__device__ float g_wB [49*64*64];     // transposed deform weights     [tap][c][oc]

// ---------------- bf16 helpers --------------------------------------------
static __device__ __forceinline__ uint32_t packbf2(float lo, float hi) {
    uint32_t r;
    asm("cvt.rn.bf16x2.f32 %0, %1, %2;" : "=r"(r) : "f"(hi), "f"(lo));
    return r;
}
static __device__ __forceinline__ void mma_bf16(float* d, const uint32_t* a,
                                                const uint32_t* b) {
    asm volatile(
        "mma.sync.aligned.m16n8k16.row.col.f32.bf16.bf16.f32 "
        "{%0,%1,%2,%3},{%4,%5,%6,%7},{%8,%9},{%0,%1,%2,%3};"
        : "+f"(d[0]), "+f"(d[1]), "+f"(d[2]), "+f"(d[3])
        : "r"(a[0]), "r"(a[1]), "r"(a[2]), "r"(a[3]), "r"(b[0]), "r"(b[1]));
}

// ---------------- weight transpose: w[O][C][K][K] -> out[tap][c][ocPad] ----
__global__ void k_transpose(const float* __restrict__ w, float* __restrict__ out,
                            int K2, int KOUT, int KOUTP) {
    int n = K2 * 64 * KOUTP;
    for (int idx = blockIdx.x * blockDim.x + threadIdx.x; idx < n;
         idx += gridDim.x * blockDim.x) {
        int oc  = idx % KOUTP;
        int c   = (idx / KOUTP) % 64;
        int tap = idx / (KOUTP * 64);
        out[idx] = (oc < KOUT) ? w[(oc * 64 + c) * K2 + tap] : 0.f;
    }
}

// ---------------- fused LayerNorm + 1x1 conv (w_in: 64 -> 128) -------------
__global__ __launch_bounds__(256) void k_ln_win(
    const float* __restrict__ x, const float* __restrict__ ln_w,
    const float* __restrict__ ln_b, const float* __restrict__ w_in,
    const float* __restrict__ b_in, float* __restrict__ out1,
    float* __restrict__ out2)
{
    __shared__ float wT[64 * 128];   // [c][o]
    __shared__ float hb[8][64];
    int tid = threadIdx.x;
    for (int idx = tid; idx < 8192; idx += 256) {
        int o = idx >> 6, c = idx & 63;
        wT[c * 128 + o] = w_in[idx];
    }
    int wp = tid >> 5, lane = tid & 31;
    int pg = blockIdx.x * 8 + wp;
    int b = pg / HW, hw = pg % HW;
    const float* xb = x + (size_t)b * CH * HW + hw;
    float v0 = xb[(size_t)lane * HW];
    float v1 = xb[(size_t)(lane + 32) * HW];
    float s = v0 + v1, q = v0 * v0 + v1 * v1;
    #pragma unroll
    for (int o = 16; o; o >>= 1) {
        s += __shfl_xor_sync(0xffffffffu, s, o);
        q += __shfl_xor_sync(0xffffffffu, q, o);
    }
    float mu  = s * (1.f / 64.f);
    float var = q * (1.f / 64.f) - mu * mu;
    float rs  = rsqrtf(var + 1e-5f);
    hb[wp][lane]      = (v0 - mu) * rs * ln_w[lane]      + ln_b[lane];
    hb[wp][lane + 32] = (v1 - mu) * rs * ln_w[lane + 32] + ln_b[lane + 32];
    __syncthreads();
    float a0 = b_in[lane], a1 = b_in[lane + 32];
    float a2 = b_in[lane + 64], a3 = b_in[lane + 96];
    #pragma unroll 8
    for (int c = 0; c < 64; c++) {
        float hv = hb[wp][c];
        const float* wr = &wT[c * 128 + lane];
        a0 += hv * wr[0];  a1 += hv * wr[32];
        a2 += hv * wr[64]; a3 += hv * wr[96];
    }
    float* o1 = out1 + (size_t)pg * 64;
    float* o2 = out2 + (size_t)pg * 64;
    o1[lane] = a0; o1[lane + 32] = a1;
    o2[lane] = a2; o2[lane + 32] = a3;
}

// ---------------- dense KxK conv, bf16 MMA, HALO-tiled ----------------------
// 16x8 px tile + halo loaded ONCE; per tap only weights reload + shifted frags.
// 8 warps = 4 pxg x 2 ocg.
template<int K, int PAD, int KOUT, int KOUTP, int SPAN>
__global__ __launch_bounds__(256) void k_conv_tc(
    const float* __restrict__ in, const float* __restrict__ wT,
    const float* __restrict__ bias, float* __restrict__ out)
{
    constexpr int HX = 16 + K - 1, HY = 8 + K - 1, HPX = HX * HY;
    constexpr int NT = SPAN / 16;
    constexpr int SPANP = SPAN + 4;
    extern __shared__ uint32_t sm[];
    uint32_t* As = sm;                 // [HPX][36] bf16x2 words (c-pairs)
    uint32_t* Bs = sm + HPX * 36;      // [32 kpair][SPANP] bf16x2 words
    int tid = threadIdx.x, lane = tid & 31, w = tid >> 5;
    int q = lane >> 2, r = lane & 3;
    int pxg = w >> 1, ocg = w & 1;
    int b = blockIdx.z;
    int ty0 = blockIdx.y * 8, tx0 = blockIdx.x * 16;
    float acc[2][NT][4] = {};

    // halo fill (once)
    for (int idx = tid; idx < HPX * 32; idx += 256) {
        int hp = idx >> 5, c2 = idx & 31;
        int hy = hp / HX, hx = hp % HX;
        int yy = ty0 + hy - PAD, xx = tx0 + hx - PAD;
        float2 val = make_float2(0.f, 0.f);
        if (yy >= 0 && yy < HH && xx >= 0 && xx < WWID)
            val = *(const float2*)(in + ((size_t)((b * HH + yy) * WWID + xx)) * 64 + 2 * c2);
        As[hp * 36 + c2] = packbf2(val.x, val.y);
    }

    for (int tap = 0; tap < K * K; tap++) {
        int ki = tap / K, kj = tap % K;
        __syncthreads();
        for (int idx = tid; idx < 32 * SPAN; idx += 256) {
            int kp = idx / SPAN, oc = idx % SPAN;
            const float* wp = wT + (size_t)tap * 64 * KOUTP + (2 * kp) * KOUTP + oc;
            Bs[kp * SPANP + oc] = packbf2(wp[0], wp[KOUTP]);
        }
        __syncthreads();
        #pragma unroll
        for (int kc = 0; kc < 4; kc++) {
            uint32_t a[2][4];
            #pragma unroll
            for (int m = 0; m < 2; m++) {
                int hbase = (pxg * 2 + m + ki) * HX + kj;
                const uint32_t* Ap = As + (hbase + q) * 36 + kc * 8 + r;
                a[m][0] = Ap[0];
                a[m][1] = Ap[8 * 36];
                a[m][2] = Ap[4];
                a[m][3] = Ap[8 * 36 + 4];
            }
            #pragma unroll
            for (int nt = 0; nt < NT; nt++) {
                uint32_t bb[2];
                int ocb = ocg * (SPAN / 2) + nt * 8 + q;
                bb[0] = Bs[(kc * 8 + r)     * SPANP + ocb];
                bb[1] = Bs[(kc * 8 + r + 4) * SPANP + ocb];
                mma_bf16(acc[0][nt], a[0], bb);
                mma_bf16(acc[1][nt], a[1], bb);
            }
        }
    }
    // store PLANAR [oc][pixel] with bias
    #pragma unroll
    for (int m = 0; m < 2; m++) {
        #pragma unroll
        for (int nt = 0; nt < NT; nt++) {
            #pragma unroll
            for (int hh = 0; hh < 2; hh++) {
                int p  = pxg * 32 + m * 16 + q + hh * 8;
                int pg = (b * HH + ty0 + (p >> 4)) * WWID + tx0 + (p & 15);
                int oc = ocg * (SPAN / 2) + nt * 8 + 2 * r;
                float v0 = acc[m][nt][hh * 2 + 0];
                float v1 = acc[m][nt][hh * 2 + 1];
                if (oc     < KOUT) out[(size_t)oc       * BHW + pg] = v0 + bias[oc];
                if (oc + 1 < KOUT) out[(size_t)(oc + 1) * BHW + pg] = v1 + bias[oc + 1];
            }
        }
    }
}

// ---------------- deformable KxK conv (Cout=64), bf16 MMA -------------------
template<int K, int PAD>
__global__ __launch_bounds__(256) void k_deform_tc(
    const float* __restrict__ in, const float* __restrict__ off,
    const float* __restrict__ wT, const float* __restrict__ bias,
    float* __restrict__ out)
{
    extern __shared__ uint32_t sm[];
    uint32_t* As = sm;                       // [128][36] bf16x2
    uint32_t* Bs = sm + 128 * 36;            // [32][68] bf16x2
    float* w00 = (float*)(Bs + 32 * 68);     // 4 x 128 bilinear weights
    float* w01 = w00 + 128;
    float* w10 = w01 + 128;
    float* w11 = w10 + 128;
    int*   s_y0 = (int*)(w11 + 128);
    int*   s_x0 = s_y0 + 128;

    int tid = threadIdx.x, lane = tid & 31, w = tid >> 5;
    int q = lane >> 2, r = lane & 3;
    int pxg = w >> 1, ocg = w & 1;
    int b = blockIdx.z;
    int ty0 = blockIdx.y * 8, tx0 = blockIdx.x * 16;
    const float* base = in + (size_t)b * HW * 64;
    float acc[2][4][4] = {};

    for (int tap = 0; tap < K * K; tap++) {
        int ki = tap / K, kj = tap % K;
        __syncthreads();
        for (int idx = tid; idx < 2048; idx += 256) {
            int kp = idx >> 6, oc = idx & 63;
            const float* wp = wT + (size_t)tap * 4096 + (2 * kp) * 64 + oc;
            Bs[kp * 68 + oc] = packbf2(wp[0], wp[64]);
        }
        if (tid < 128) {
            int p  = tid;
            int yy = ty0 + (p >> 4), xx = tx0 + (p & 15);
            int pg = (b * HH + yy) * WWID + xx;
            float oy = off[(size_t)(2 * tap)     * BHW + pg];
            float ox = off[(size_t)(2 * tap + 1) * BHW + pg];
            float py = (float)(yy + ki - PAD) + oy;
            float px = (float)(xx + kj - PAD) + ox;
            float fy = floorf(py), fx = floorf(px);
            float wy = py - fy,    wx = px - fx;
            s_y0[p] = (int)fy; s_x0[p] = (int)fx;
            w00[p] = (1.f - wy) * (1.f - wx);
            w01[p] = (1.f - wy) * wx;
            w10[p] = wy * (1.f - wx);
            w11[p] = wy * wx;
        }
        __syncthreads();
        #pragma unroll 4
        for (int it = 0; it < 16; it++) {
            int v  = it * 256 + tid;
            int p  = v >> 5, c2 = v & 31;
            int y0 = s_y0[p], x0 = s_x0[p];
            float a00 = w00[p], a01 = w01[p], a10 = w10[p], a11 = w11[p];
            bool yv0 = (unsigned)y0       < HH;
            bool yv1 = (unsigned)(y0 + 1) < HH;
            bool xv0 = (unsigned)x0       < WWID;
            bool xv1 = (unsigned)(x0 + 1) < WWID;
            long long r0 = ((long long)y0 * WWID + x0) * 64 + 2 * c2;
            float2 v00 = make_float2(0.f, 0.f), v01 = v00, v10 = v00, v11 = v00;
            if (yv0 && xv0) v00 = *(const float2*)(base + r0);
            if (yv0 && xv1) v01 = *(const float2*)(base + r0 + 64);
            if (yv1 && xv0) v10 = *(const float2*)(base + r0 + 64 * WWID);
            if (yv1 && xv1) v11 = *(const float2*)(base + r0 + 64 * WWID + 64);
            float rx = a00 * v00.x + a01 * v01.x + a10 * v10.x + a11 * v11.x;
            float ry = a00 * v00.y + a01 * v01.y + a10 * v10.y + a11 * v11.y;
            As[p * 36 + c2] = packbf2(rx, ry);
        }
        __syncthreads();
        #pragma unroll
        for (int kc = 0; kc < 4; kc++) {
            uint32_t a[2][4];
            #pragma unroll
            for (int m = 0; m < 2; m++) {
                int pr = pxg * 32 + m * 16;
                const uint32_t* Ap = As + (pr + q) * 36 + kc * 8 + r;
                a[m][0] = Ap[0];
                a[m][1] = Ap[8 * 36];
                a[m][2] = Ap[4];
                a[m][3] = Ap[8 * 36 + 4];
            }
            #pragma unroll
            for (int nt = 0; nt < 4; nt++) {
                uint32_t bb[2];
                int ocb = ocg * 32 + nt * 8 + q;
                bb[0] = Bs[(kc * 8 + r)     * 68 + ocb];
                bb[1] = Bs[(kc * 8 + r + 4) * 68 + ocb];
                mma_bf16(acc[0][nt], a[0], bb);
                mma_bf16(acc[1][nt], a[1], bb);
            }
        }
    }
    #pragma unroll
    for (int m = 0; m < 2; m++) {
        #pragma unroll
        for (int nt = 0; nt < 4; nt++) {
            #pragma unroll
            for (int hh = 0; hh < 2; hh++) {
                int p  = pxg * 32 + m * 16 + q + hh * 8;
                int pg = (b * HH + ty0 + (p >> 4)) * WWID + tx0 + (p & 15);
                int oc = ocg * 32 + nt * 8 + 2 * r;
                float2 v;
                v.x = acc[m][nt][hh * 2 + 0] + bias[oc];
                v.y = acc[m][nt][hh * 2 + 1] + bias[oc + 1];
                *(float2*)(out + (size_t)pg * 64 + oc) = v;
            }
        }
    }
}

// ---------------- final: (x1+x2) @ w_out^T + b_out + residual x, NCHW out ---
__global__ __launch_bounds__(256) void k_final(
    const float* __restrict__ x1, const float* __restrict__ x2,
    const float* __restrict__ xin, const float* __restrict__ w_out,
    const float* __restrict__ b_out, float* __restrict__ out)
{
    __shared__ float st[64 * 65];
    __shared__ float ws[64 * 64];   // [c][o]
    int tid = threadIdx.x;
    size_t p0 = (size_t)blockIdx.x * 64;
    for (int idx = tid; idx < 4096; idx += 256) {
        int o = idx >> 6, c = idx & 63;
        ws[c * 64 + o] = w_out[idx];
    }
    #pragma unroll
    for (int i = 0; i < 16; i++) {
        int v = i * 256 + tid;
        int p = v >> 6, c = v & 63;
        st[p * 65 + c] = x1[(p0 + p) * 64 + c] + x2[(p0 + p) * 64 + c];
    }
    __syncthreads();
    int pxg = tid >> 4, ocg = tid & 15;
    float acc[4][4] = {};
    #pragma unroll 4
    for (int c = 0; c < 64; c++) {
        float iv[4];
        #pragma unroll
        for (int i = 0; i < 4; i++) iv[i] = st[(pxg * 4 + i) * 65 + c];
        #pragma unroll
        for (int j = 0; j < 4; j++) {
            float wv = ws[c * 64 + ocg * 4 + j];
            #pragma unroll
            for (int i = 0; i < 4; i++) acc[i][j] += iv[i] * wv;
        }
    }
    int b = (int)(p0 / HW);
    int hwbase = (int)(p0 % HW);
    #pragma unroll
    for (int i = 0; i < 4; i++) {
        int hw = hwbase + pxg * 4 + i;
        #pragma unroll
        for (int j = 0; j < 4; j++) {
            int oc = ocg * 4 + j;
            size_t a = ((size_t)b * 64 + oc) * HW + hw;
            out[a] = acc[i][j] + b_out[oc] + xin[a];
        }
    }
}

// ---------------- launch --------------------------------------------------
extern "C" void kernel_launch(void* const* d_in, const int* in_sizes, int n_in,
                              void* d_out, int out_size) {
    const float* x    = (const float*)d_in[0];
    const float* ln_w = (const float*)d_in[1];
    const float* ln_b = (const float*)d_in[2];
    const float* w_in = (const float*)d_in[3];
    const float* b_in = (const float*)d_in[4];
    const float* w_out= (const float*)d_in[5];
    const float* b_out= (const float*)d_in[6];
    const float* dw1  = (const float*)d_in[7];
    const float* db1  = (const float*)d_in[8];
    const float* dw2  = (const float*)d_in[9];
    const float* db2  = (const float*)d_in[10];
    const float* dw3  = (const float*)d_in[11];
    const float* db3  = (const float*)d_in[12];
    const float* ow1  = (const float*)d_in[13];
    const float* ob1  = (const float*)d_in[14];
    const float* ow2  = (const float*)d_in[15];
    const float* ob2  = (const float*)d_in[16];
    const float* ow3  = (const float*)d_in[17];
    const float* ob3  = (const float*)d_in[18];
    float* out = (float*)d_out;

    float *px1, *px2, *py, *poff, *pwA, *pwB;
    cudaGetSymbolAddress((void**)&px1,  g_x1);
    cudaGetSymbolAddress((void**)&px2,  g_x2);
    cudaGetSymbolAddress((void**)&py,   g_y);
    cudaGetSymbolAddress((void**)&poff, g_off);
    cudaGetSymbolAddress((void**)&pwA,  g_wA);
    cudaGetSymbolAddress((void**)&pwB,  g_wB);

    const int SMC1 = (20 * 12 * 36 + 32 * 132) * 4;
    const int SMC2 = (20 * 12 * 36 + 32 * 68)  * 4;
    const int SMC3 = (18 * 10 * 36 + 32 * 36)  * 4;
    const int SMD  = (128 * 36 + 32 * 68) * 4 + 128 * 6 * 4;

    cudaFuncSetAttribute(k_conv_tc<5,2,98,128,128>, cudaFuncAttributeMaxDynamicSharedMemorySize, SMC1);
    cudaFuncSetAttribute(k_conv_tc<5,2,50,64,64>,   cudaFuncAttributeMaxDynamicSharedMemorySize, SMC2);
    cudaFuncSetAttribute(k_conv_tc<3,1,18,32,32>,   cudaFuncAttributeMaxDynamicSharedMemorySize, SMC3);
    cudaFuncSetAttribute(k_deform_tc<7,3>, cudaFuncAttributeMaxDynamicSharedMemorySize, SMD);
    cudaFuncSetAttribute(k_deform_tc<5,2>, cudaFuncAttributeMaxDynamicSharedMemorySize, SMD);
    cudaFuncSetAttribute(k_deform_tc<3,1>, cudaFuncAttributeMaxDynamicSharedMemorySize, SMD);

    dim3 tiles(WWID / 16, HH / 8, BATCH);   // 16x8 px tiles

    k_ln_win<<<BHW / 8, 256>>>(x, ln_w, ln_b, w_in, b_in, px1, px2);

    // stage 1: offset conv 5x5 -> 98, deform 7x7
    k_transpose<<<256, 256>>>(ow1, pwA, 25, 98, 128);
    k_conv_tc<5,2,98,128,128><<<tiles, 256, SMC1>>>(px1, pwA, ob1, poff);
    k_transpose<<<256, 256>>>(dw1, pwB, 49, 64, 64);
    k_deform_tc<7,3><<<tiles, 256, SMD>>>(px1, poff, pwB, db1, py);

    // stage 2: offset conv 5x5 -> 50, deform 5x5
    k_transpose<<<256, 256>>>(ow2, pwA, 25, 50, 64);
    k_conv_tc<5,2,50,64,64><<<tiles, 256, SMC2>>>(py, pwA, ob2, poff);
    k_transpose<<<256, 256>>>(dw2, pwB, 25, 64, 64);
    k_deform_tc<5,2><<<tiles, 256, SMD>>>(py, poff, pwB, db2, px1);

    // stage 3: offset conv 3x3 -> 18, deform 3x3
    k_transpose<<<256, 256>>>(ow3, pwA, 9, 18, 32);
    k_conv_tc<3,1,18,32,32><<<tiles, 256, SMC3>>>(px1, pwA, ob3, poff);
    k_transpose<<<256, 256>>>(dw3, pwB, 9, 64, 64);
    k_deform_tc<3,1><<<tiles, 256, SMD>>>(px1, poff, pwB, db3, py);

    k_final<<<BHW / 64, 256>>>(py, px2, x, w_out, b_out, out);
}